// round 6
// baseline (speedup 1.0000x reference)
#include <cuda_runtime.h>

// Integer-exact fused QAT conv stack (bit-exact vs fp32 reference).
// Each thread: 8 output positions end-to-end, rolling y-window (3 deep).
// Occupancy-first: __launch_bounds__(256,6) -> ~42 regs, 6 blocks/SM.

#define NT 256   // threads per block
#define PP 8     // output positions per thread

__device__ __forceinline__ int cvtrd(float v) {
    return __float2int_rd(fmaf(v, 128.0f, 0.5f));   // floor(v*128 + 0.5)
}
__device__ __forceinline__ int packsat2(int a, int b, int c) {
    int d;
    asm("cvt.pack.sat.s8.s32.b32 %0, %1, %2, %3;"
        : "=r"(d) : "r"(a), "r"(b), "r"(c));
    return d;
}
// bytes [v0,v1,v2,v3]; same helper for weights and data -> dp4a order-invariant
__device__ __forceinline__ int pack4sat(int v0, int v1, int v2, int v3) {
    return packsat2(v1, v0, packsat2(v3, v2, 0));
}
__device__ __forceinline__ int qpack(float a, float b, float c, float d) {
    return pack4sat(cvtrd(a), cvtrd(b), cvtrd(c), cvtrd(d));
}

// wall layout: [0..23] w1 packed (oc*3+k), [24..31] 128*b1+64,
//              [32..43] w2 packed (oc*6+k*2+h), [44..45] 128*b2+64
__device__ __forceinline__ void y_one(int x0, int x1, int x2,
                                      const int* wall, int& lo, int& hi)
{
    int yv[8];
#pragma unroll
    for (int oc = 0; oc < 8; oc++) {
        int acc = __dp4a(x0, wall[oc * 3 + 0], wall[24 + oc]);
        acc     = __dp4a(x1, wall[oc * 3 + 1], acc);
        acc     = __dp4a(x2, wall[oc * 3 + 2], acc);
        yv[oc]  = acc >> 7;
    }
    lo = pack4sat(yv[0], yv[1], yv[2], yv[3]);
    hi = pack4sat(yv[4], yv[5], yv[6], yv[7]);
}

template <bool GUARD>
__device__ __forceinline__ void tail_compute(
    const int* xw, const int* wall, int base, int L, float* ob)
{
    int yl[3], yh[3];
    // y window preload: y(i) lives at position base-1+i
    y_one(xw[0], xw[1], xw[2], wall, yl[0], yh[0]);
    if (GUARD && (base - 1 < 0)) { yl[0] = 0; yh[0] = 0; }
    y_one(xw[1], xw[2], xw[3], wall, yl[1], yh[1]);

    float fo0[4], fo1[4];
#pragma unroll
    for (int p = 0; p < PP; p++) {
        const int i0 = p % 3, i1 = (p + 1) % 3, i2 = (p + 2) % 3;
        y_one(xw[p + 2], xw[p + 3], xw[p + 4], wall, yl[i2], yh[i2]);
        if (GUARD && (base + 1 + p >= L)) { yl[i2] = 0; yh[i2] = 0; }

        int a0 = __dp4a(yl[i0], wall[32], wall[44]);
        a0     = __dp4a(yh[i0], wall[33], a0);
        a0     = __dp4a(yl[i1], wall[34], a0);
        a0     = __dp4a(yh[i1], wall[35], a0);
        a0     = __dp4a(yl[i2], wall[36], a0);
        a0     = __dp4a(yh[i2], wall[37], a0);
        int a1 = __dp4a(yl[i0], wall[38], wall[45]);
        a1     = __dp4a(yh[i0], wall[39], a1);
        a1     = __dp4a(yl[i1], wall[40], a1);
        a1     = __dp4a(yh[i1], wall[41], a1);
        a1     = __dp4a(yl[i2], wall[42], a1);
        a1     = __dp4a(yh[i2], wall[43], a1);
        fo0[p & 3] = (float)min(max(a0 >> 7, -128), 127) * 0.0078125f;
        fo1[p & 3] = (float)min(max(a1 >> 7, -128), 127) * 0.0078125f;

        if ((p & 3) == 3) {   // flush every 4 positions
            int o = base + p - 3;
            *(float4*)(ob + o) = make_float4(fo0[0], fo0[1], fo0[2], fo0[3]);
            *(float4*)(ob + (size_t)L + o) =
                make_float4(fo1[0], fo1[1], fo1[2], fo1[3]);
        }
    }
}

__global__ __launch_bounds__(NT, 6) void fused_qconv_roll(
    const float* __restrict__ x,
    const float* __restrict__ w1, const float* __restrict__ b1,
    const float* __restrict__ gamma, const float* __restrict__ beta,
    const float* __restrict__ bn_mean, const float* __restrict__ bn_var,
    const float* __restrict__ w2, const float* __restrict__ b2,
    float* __restrict__ out, int L)
{
    __shared__ int wall[48];
    const int tid = threadIdx.x;

    // ---- weight prep (tiny, once per block) ----
    if (tid < 24) {
        int oc = tid / 3, k = tid % 3;
        float sf = (float)((double)gamma[oc] / sqrt((double)bn_var[oc] + 1e-5));
        const float* wb = w1 + oc * 12 + k;
        wall[tid] = qpack(wb[0] * sf, wb[3] * sf, wb[6] * sf, wb[9] * sf);
    } else if (tid < 32) {
        int oc = tid - 24;
        float sf = (float)((double)gamma[oc] / sqrt((double)bn_var[oc] + 1e-5));
        int bi = min(max(cvtrd((b1[oc] - bn_mean[oc]) * sf + beta[oc]), -128), 127);
        wall[tid] = bi * 128 + 64;
    } else if (tid < 44) {
        int t = tid - 32, oc = t / 6, r = t % 6, k = r >> 1, h = r & 1;
        const float* wb = w2 + oc * 24 + h * 12 + k;
        wall[tid] = qpack(wb[0], wb[3], wb[6], wb[9]);
    } else if (tid < 46) {
        wall[tid] = min(max(cvtrd(b2[tid - 44]), -128), 127) * 128 + 64;
    }
    __syncthreads();

    const int bb   = blockIdx.y;
    const int base = (blockIdx.x * NT + tid) * PP;   // first z position
    const float* xb = x + (size_t)bb * 4 * L;
    float* ob = out + (size_t)bb * 2 * L;

    int xw[12];   // packed fq(x), xw[j] = position base-2+j

    if (base >= 4 && base + 12 <= L) {
        // ---- fast path: 4 aligned float4 loads per channel ----
        const float* p0 = xb + (base - 4);
        const float* p1 = p0 + (size_t)L;
        const float* p2 = p0 + (size_t)2 * L;
        const float* p3 = p0 + (size_t)3 * L;

        float4 a0 = *(const float4*)(p0 +  0), a1 = *(const float4*)(p0 +  4);
        float4 a2 = *(const float4*)(p0 +  8), a3 = *(const float4*)(p0 + 12);
        float4 b0 = *(const float4*)(p1 +  0), b1v = *(const float4*)(p1 +  4);
        float4 b2v = *(const float4*)(p1 + 8), b3 = *(const float4*)(p1 + 12);
        float4 c0 = *(const float4*)(p2 +  0), c1 = *(const float4*)(p2 +  4);
        float4 c2 = *(const float4*)(p2 +  8), c3 = *(const float4*)(p2 + 12);
        float4 d0 = *(const float4*)(p3 +  0), d1 = *(const float4*)(p3 +  4);
        float4 d2 = *(const float4*)(p3 +  8), d3 = *(const float4*)(p3 + 12);

        xw[0]  = qpack(a0.z, b0.z,  c0.z, d0.z);
        xw[1]  = qpack(a0.w, b0.w,  c0.w, d0.w);
        xw[2]  = qpack(a1.x, b1v.x, c1.x, d1.x);
        xw[3]  = qpack(a1.y, b1v.y, c1.y, d1.y);
        xw[4]  = qpack(a1.z, b1v.z, c1.z, d1.z);
        xw[5]  = qpack(a1.w, b1v.w, c1.w, d1.w);
        xw[6]  = qpack(a2.x, b2v.x, c2.x, d2.x);
        xw[7]  = qpack(a2.y, b2v.y, c2.y, d2.y);
        xw[8]  = qpack(a2.z, b2v.z, c2.z, d2.z);
        xw[9]  = qpack(a2.w, b2v.w, c2.w, d2.w);
        xw[10] = qpack(a3.x, b3.x,  c3.x, d3.x);
        xw[11] = qpack(a3.y, b3.y,  c3.y, d3.y);

        tail_compute<false>(xw, wall, base, L, ob);
    } else {
        // ---- slow path: batch-row edges only ----
#pragma unroll
        for (int j = 0; j < 12; j++) {
            int p = base - 2 + j, w = 0;
            if (p >= 0 && p < L)
                w = qpack(xb[p], xb[(size_t)L + p],
                          xb[(size_t)2 * L + p], xb[(size_t)3 * L + p]);
            xw[j] = w;
        }
        tail_compute<true>(xw, wall, base, L, ob);
    }
}

extern "C" void kernel_launch(void* const* d_in, const int* in_sizes, int n_in,
                              void* d_out, int out_size)
{
    const float* x       = (const float*)d_in[0];
    const float* w1      = (const float*)d_in[1];
    const float* b1      = (const float*)d_in[2];
    const float* gamma   = (const float*)d_in[3];
    const float* beta    = (const float*)d_in[4];
    const float* bn_mean = (const float*)d_in[5];
    const float* bn_var  = (const float*)d_in[6];
    const float* w2      = (const float*)d_in[7];
    const float* b2      = (const float*)d_in[8];
    float* out = (float*)d_out;

    const int B = 16;
    const int L = in_sizes[0] / (B * 4);

    dim3 grid(L / (NT * PP), B);
    fused_qconv_roll<<<grid, NT>>>(
        x, w1, b1, gamma, beta, bn_mean, bn_var, w2, b2, out, L);
}

// round 7
// speedup vs baseline: 1.1028x; 1.1028x over previous
#include <cuda_runtime.h>
#include <cstdint>

// Integer-exact fused QAT conv stack (bit-exact vs fp32 reference).
// Persistent blocks + cp.async.bulk double-buffered x tiles in smem.
// Compute: R4's all-register DP4A body fed from shared memory.

#define NT     256
#define PP     8
#define TILE   (NT * PP)          // 2048 positions
#define HALO   8
#define ROWF   (TILE + 2 * HALO)  // 2064 floats per channel row
#define STAGES 2
#define BATCH  16

__device__ __forceinline__ int cvtrd(float v) {
    return __float2int_rd(fmaf(v, 128.0f, 0.5f));   // floor(v*128 + 0.5)
}
__device__ __forceinline__ int packsat2(int a, int b, int c) {
    int d;
    asm("cvt.pack.sat.s8.s32.b32 %0, %1, %2, %3;"
        : "=r"(d) : "r"(a), "r"(b), "r"(c));
    return d;
}
// bytes [v0,v1,v2,v3]; same helper for weights and data -> dp4a order-invariant
__device__ __forceinline__ int pack4sat(int v0, int v1, int v2, int v3) {
    return packsat2(v1, v0, packsat2(v3, v2, 0));
}
__device__ __forceinline__ int qpack(float a, float b, float c, float d) {
    return pack4sat(cvtrd(a), cvtrd(b), cvtrd(c), cvtrd(d));
}

__device__ __forceinline__ uint32_t s2u(const void* p) {
    uint32_t a;
    asm("{ .reg .u64 t; cvta.to.shared.u64 t, %1; cvt.u32.u64 %0, t; }"
        : "=r"(a) : "l"(p));
    return a;
}
__device__ __forceinline__ void mbar_init(uint32_t a, uint32_t cnt) {
    asm volatile("mbarrier.init.shared.b64 [%0], %1;" :: "r"(a), "r"(cnt) : "memory");
}
__device__ __forceinline__ void mbar_arrive(uint32_t a) {
    asm volatile("mbarrier.arrive.shared.b64 _, [%0];" :: "r"(a) : "memory");
}
__device__ __forceinline__ void mbar_expect(uint32_t a, uint32_t bytes) {
    asm volatile("mbarrier.arrive.expect_tx.shared.b64 _, [%0], %1;"
                 :: "r"(a), "r"(bytes) : "memory");
}
__device__ __forceinline__ void mbar_wait_acq(uint32_t a, int par) {
    asm volatile(
        "{\n\t.reg .pred P;\n"
        "W_%=:\n\t"
        "mbarrier.try_wait.parity.acquire.cta.shared::cta.b64 P, [%0], %1, 0x989680;\n\t"
        "@P bra D_%=;\n\t"
        "bra W_%=;\n"
        "D_%=:\n\t}"
        :: "r"(a), "r"(par) : "memory");
}
__device__ __forceinline__ void mbar_wait_rlx(uint32_t a, int par) {
    asm volatile(
        "{\n\t.reg .pred P;\n"
        "W_%=:\n\t"
        "mbarrier.try_wait.parity.relaxed.cta.shared::cta.b64 P, [%0], %1, 0x989680;\n\t"
        "@P bra D_%=;\n\t"
        "bra W_%=;\n"
        "D_%=:\n\t}"
        :: "r"(a), "r"(par) : "memory");
}
__device__ __forceinline__ void bulk_g2s(uint32_t dst, const void* src,
                                         uint32_t bytes, uint32_t mbar) {
    asm volatile(
        "cp.async.bulk.shared::cta.global.mbarrier::complete_tx::bytes "
        "[%0], [%1], %2, [%3];"
        :: "r"(dst), "l"(src), "r"(bytes), "r"(mbar) : "memory");
}

// wall layout: [0..23] w1 packed (oc*3+k), [24..31] 128*b1+64,
//              [32..43] w2 packed (oc*6+k*2+h), [44..45] 128*b2+64
template <bool GUARD>
__device__ __forceinline__ void tail_compute(
    const int* xw, const int* wall, int base, int L, float* ob)
{
    int yl[PP + 2], yh[PP + 2];
#pragma unroll
    for (int i = 0; i < PP + 2; i++) {
        int x0 = xw[i], x1 = xw[i + 1], x2 = xw[i + 2];
        int yv[8];
#pragma unroll
        for (int oc = 0; oc < 8; oc++) {
            int acc = __dp4a(x0, wall[oc * 3 + 0], wall[24 + oc]);
            acc     = __dp4a(x1, wall[oc * 3 + 1], acc);
            acc     = __dp4a(x2, wall[oc * 3 + 2], acc);
            yv[oc]  = acc >> 7;
        }
        int lo = pack4sat(yv[0], yv[1], yv[2], yv[3]);
        int hi = pack4sat(yv[4], yv[5], yv[6], yv[7]);
        if (GUARD) {
            int q = base - 1 + i;
            bool valid = (q >= 0) && (q < L);
            lo = valid ? lo : 0;
            hi = valid ? hi : 0;
        }
        yl[i] = lo; yh[i] = hi;
    }

    float f0[PP], f1[PP];
#pragma unroll
    for (int p = 0; p < PP; p++) {
        int a0 = __dp4a(yl[p],     wall[32], wall[44]);
        a0     = __dp4a(yh[p],     wall[33], a0);
        a0     = __dp4a(yl[p + 1], wall[34], a0);
        a0     = __dp4a(yh[p + 1], wall[35], a0);
        a0     = __dp4a(yl[p + 2], wall[36], a0);
        a0     = __dp4a(yh[p + 2], wall[37], a0);
        int a1 = __dp4a(yl[p],     wall[38], wall[45]);
        a1     = __dp4a(yh[p],     wall[39], a1);
        a1     = __dp4a(yl[p + 1], wall[40], a1);
        a1     = __dp4a(yh[p + 1], wall[41], a1);
        a1     = __dp4a(yl[p + 2], wall[42], a1);
        a1     = __dp4a(yh[p + 2], wall[43], a1);
        f0[p] = (float)min(max(a0 >> 7, -128), 127) * 0.0078125f;
        f1[p] = (float)min(max(a1 >> 7, -128), 127) * 0.0078125f;
    }
    *(float4*)(ob + base)     = make_float4(f0[0], f0[1], f0[2], f0[3]);
    *(float4*)(ob + base + 4) = make_float4(f0[4], f0[5], f0[6], f0[7]);
    *(float4*)(ob + (size_t)L + base)     = make_float4(f1[0], f1[1], f1[2], f1[3]);
    *(float4*)(ob + (size_t)L + base + 4) = make_float4(f1[4], f1[5], f1[6], f1[7]);
}

__global__ __launch_bounds__(NT) void fused_qconv_pipe(
    const float* __restrict__ x,
    const float* __restrict__ w1, const float* __restrict__ b1,
    const float* __restrict__ gamma, const float* __restrict__ beta,
    const float* __restrict__ bn_mean, const float* __restrict__ bn_var,
    const float* __restrict__ w2, const float* __restrict__ b2,
    float* __restrict__ out, int L)
{
    extern __shared__ float dsm[];            // [STAGES][4][ROWF]
    __shared__ __align__(8) uint64_t mbar[2 * STAGES];  // full[0..1], empty[0..1]
    __shared__ int wall[48];
    const int tid = threadIdx.x;

    // ---- weight prep ----
    if (tid < 24) {
        int oc = tid / 3, k = tid % 3;
        float sf = (float)((double)gamma[oc] / sqrt((double)bn_var[oc] + 1e-5));
        const float* wb = w1 + oc * 12 + k;
        wall[tid] = qpack(wb[0] * sf, wb[3] * sf, wb[6] * sf, wb[9] * sf);
    } else if (tid < 32) {
        int oc = tid - 24;
        float sf = (float)((double)gamma[oc] / sqrt((double)bn_var[oc] + 1e-5));
        int bi = min(max(cvtrd((b1[oc] - bn_mean[oc]) * sf + beta[oc]), -128), 127);
        wall[tid] = bi * 128 + 64;
    } else if (tid < 44) {
        int t = tid - 32, oc = t / 6, r = t % 6, k = r >> 1, h = r & 1;
        const float* wb = w2 + oc * 24 + h * 12 + k;
        wall[tid] = qpack(wb[0], wb[3], wb[6], wb[9]);
    } else if (tid < 46) {
        wall[tid] = min(max(cvtrd(b2[tid - 44]), -128), 127) * 128 + 64;
    }

    uint32_t fullb[STAGES], emptyb[STAGES];
#pragma unroll
    for (int s = 0; s < STAGES; s++) {
        fullb[s]  = s2u(&mbar[s]);
        emptyb[s] = s2u(&mbar[STAGES + s]);
    }
    if (tid == 0) {
#pragma unroll
        for (int s = 0; s < STAGES; s++) {
            mbar_init(fullb[s], 1);      // completes via expect_tx + tx bytes
            mbar_init(emptyb[s], NT);    // all threads arrive after consuming
        }
    }
    __syncthreads();

    const int tpr    = L / TILE;          // tiles per batch row
    const int ntiles = BATCH * tpr;
    const int G      = gridDim.x;
    const int bid    = blockIdx.x;
    const int n_my   = (bid < ntiles) ? (ntiles - bid + G - 1) / G : 0;

    uint32_t stage_addr[STAGES];
#pragma unroll
    for (int s = 0; s < STAGES; s++) stage_addr[s] = s2u(dsm + s * 4 * ROWF);

    // producer: issue tile index i (of this block's sequence) into slot
    auto issue = [&](int i, int slot) {
        int t  = bid + i * G;
        int bb = t / tpr, tr = t - bb * tpr;
        int ts = tr * TILE;
        int start = ts - HALO; if (start < 0) start = 0;
        int end   = ts + TILE + HALO; if (end > L) end = L;
        uint32_t nb = (uint32_t)(end - start) * 4u;
        uint32_t dst_off = (uint32_t)(start - (ts - HALO)) * 4u;
        const float* xb = x + (size_t)bb * 4 * L;
        mbar_expect(fullb[slot], nb * 4u);
#pragma unroll
        for (int c = 0; c < 4; c++)
            bulk_g2s(stage_addr[slot] + c * (ROWF * 4) + dst_off,
                     xb + (size_t)c * L + start, nb, fullb[slot]);
    };

    if (tid == 0) {    // prologue: first empty-waits pass trivially (phase 1)
        if (n_my > 0) issue(0, 0);
        if (n_my > 1) issue(1, 1);
    }

    int cs = 0, cp = 0;   // consumer cursor (stage, phase)
    for (int i = 0; i < n_my; i++) {
        int t  = bid + i * G;
        int bb = t / tpr, tr = t - bb * tpr;
        int ts = tr * TILE;
        bool edge = (tr == 0) || (tr == tpr - 1);

        mbar_wait_acq(fullb[cs], cp);

        float* xs = dsm + cs * 4 * ROWF;
        if (edge) {
            if (tid < 32) {     // zero-fill the out-of-range halo words
                int c = tid >> 3, o = tid & 7;
                if (tr == 0)       xs[c * ROWF + o] = 0.0f;
                if (tr == tpr - 1) xs[c * ROWF + (ROWF - 8) + o] = 0.0f;
            }
            __syncthreads();
        }

        const int base = ts + tid * PP;
        const float* r0 = xs + 0 * ROWF + tid * PP + 4;
        const float* r1 = xs + 1 * ROWF + tid * PP + 4;
        const float* r2 = xs + 2 * ROWF + tid * PP + 4;
        const float* r3 = xs + 3 * ROWF + tid * PP + 4;

        float4 a0 = *(const float4*)(r0 + 0),  a1 = *(const float4*)(r0 + 4);
        float4 a2 = *(const float4*)(r0 + 8),  a3 = *(const float4*)(r0 + 12);
        float4 b0 = *(const float4*)(r1 + 0),  b1v = *(const float4*)(r1 + 4);
        float4 b2v = *(const float4*)(r1 + 8), b3 = *(const float4*)(r1 + 12);
        float4 c0 = *(const float4*)(r2 + 0),  c1 = *(const float4*)(r2 + 4);
        float4 c2 = *(const float4*)(r2 + 8),  c3 = *(const float4*)(r2 + 12);
        float4 d0 = *(const float4*)(r3 + 0),  d1 = *(const float4*)(r3 + 4);
        float4 d2 = *(const float4*)(r3 + 8),  d3 = *(const float4*)(r3 + 12);

        int xw[12];   // xw[j] = packed fq(x) at position base-2+j
        xw[0]  = qpack(a0.z, b0.z,  c0.z, d0.z);
        xw[1]  = qpack(a0.w, b0.w,  c0.w, d0.w);
        xw[2]  = qpack(a1.x, b1v.x, c1.x, d1.x);
        xw[3]  = qpack(a1.y, b1v.y, c1.y, d1.y);
        xw[4]  = qpack(a1.z, b1v.z, c1.z, d1.z);
        xw[5]  = qpack(a1.w, b1v.w, c1.w, d1.w);
        xw[6]  = qpack(a2.x, b2v.x, c2.x, d2.x);
        xw[7]  = qpack(a2.y, b2v.y, c2.y, d2.y);
        xw[8]  = qpack(a2.z, b2v.z, c2.z, d2.z);
        xw[9]  = qpack(a2.w, b2v.w, c2.w, d2.w);
        xw[10] = qpack(a3.x, b3.x,  c3.x, d3.x);
        xw[11] = qpack(a3.y, b3.y,  c3.y, d3.y);

        float* ob = out + (size_t)bb * 2 * L;
        if (edge) tail_compute<true >(xw, wall, base, L, ob);
        else      tail_compute<false>(xw, wall, base, L, ob);

        mbar_arrive(emptyb[cs]);      // release: reads above done

        if (tid == 0 && i + STAGES < n_my) {
            // empty[cs] phase cp completes when all NT threads arrived
            mbar_wait_rlx(emptyb[cs], cp);   // post-wait access is async-proxy only
            issue(i + STAGES, cs);
        }

        if (++cs == STAGES) { cs = 0; cp ^= 1; }
    }
}

extern "C" void kernel_launch(void* const* d_in, const int* in_sizes, int n_in,
                              void* d_out, int out_size)
{
    const float* x       = (const float*)d_in[0];
    const float* w1      = (const float*)d_in[1];
    const float* b1      = (const float*)d_in[2];
    const float* gamma   = (const float*)d_in[3];
    const float* beta    = (const float*)d_in[4];
    const float* bn_mean = (const float*)d_in[5];
    const float* bn_var  = (const float*)d_in[6];
    const float* w2      = (const float*)d_in[7];
    const float* b2      = (const float*)d_in[8];
    float* out = (float*)d_out;

    const int B = 16;
    const int L = in_sizes[0] / (B * 4);

    const int smem_bytes = STAGES * 4 * ROWF * (int)sizeof(float);  // 66048
    cudaFuncSetAttribute(fused_qconv_pipe,
                         cudaFuncAttributeMaxDynamicSharedMemorySize, smem_bytes);

    const int grid = 148 * 3;   // persistent, 3 blocks/SM target
    fused_qconv_pipe<<<grid, NT, smem_bytes>>>(
        x, w1, b1, gamma, beta, bn_mean, bn_var, w2, b2, out, L);
}